// round 4
// baseline (speedup 1.0000x reference)
#include <cuda_runtime.h>
#include <cuda_bf16.h>
#include <cstdint>

// ---------------------------------------------------------------------------
// Swin shifted-window attention, B=32 H=W=56 C=512 NH=16 HD=32 WS=7 SS=3
// fp32 SIMT pipeline:
//   k0: build row-index table (shift + window partition bijection)
//   k1: QKV GEMM  (gather-A)    X[100352,512] @ Wqkv^T[512,1536] + b -> g_qkv
//   k2: attention per (window, head)                              -> g_att
//   k3: proj GEMM (A = g_att global, scatter-C) @ Wp^T + b        -> out
//
// FIX vs previous round: the proj GEMM was receiving the HOST shadow address
// of the __device__ global g_att (passed as a kernel argument from host
// code). On GB300, ATS made that a silent read of zero host memory instead
// of a fault. The PROJ path now references g_att directly inside the kernel.
// ---------------------------------------------------------------------------

#define BATCH   32
#define IMG     56
#define CCH     512
#define NHEAD   16
#define HD      32
#define WS      7
#define SS      3
#define NTOK    49            // WS*WS
#define NWH     8             // IMG/WS
#define NWIN    64            // per image
#define TOTWIN  2048          // BATCH*NWIN
#define MROWS   100352        // TOTWIN*NTOK
#define QKVC    1536

// scratch (device globals: allocation-free)
__device__ float g_qkv[(size_t)MROWS * QKVC];   // 617 MB
__device__ float g_att[(size_t)MROWS * CCH];    // 205 MB
__device__ int   g_rowidx[MROWS];

// ---------------------------------------------------------------------------
__global__ void build_rowidx_kernel() {
    int m = blockIdx.x * 256 + threadIdx.x;
    if (m >= MROWS) return;
    int win = m / NTOK, n = m % NTOK;
    int b  = win >> 6, wi = win & 63;
    int wh = wi >> 3,  ww = wi & 7;
    int r = wh * WS + n / WS;
    int c = ww * WS + n % WS;
    int sh = r + SS; if (sh >= IMG) sh -= IMG;
    int sw = c + SS; if (sw >= IMG) sw -= IMG;
    g_rowidx[m] = (b * IMG + sh) * IMG + sw;
}

// ---------------------------------------------------------------------------
// Tiled fp32 GEMM: C[M,N] = A[M,512] * W[N,512]^T + bias[N]
// BM=BN=128, BK=8, 256 threads, 8x8 per-thread tile, double-buffered smem.
// QKV mode: A = x (param), rows gathered via g_rowidx, C -> g_qkv (ld 1536).
// PROJ mode: A = g_att (device global, addressed IN-KERNEL),
//            C scattered through g_rowidx into out.
// ---------------------------------------------------------------------------
template <bool QKV>
__global__ __launch_bounds__(256, 2)
void gemm_kernel(const float* __restrict__ Ain,
                 const float* __restrict__ W,
                 const float* __restrict__ bias,
                 float* __restrict__ out)
{
    __shared__ float As[2][8][128];
    __shared__ float Bs[2][8][128];

    const int tid = threadIdx.x;
    const int bm = blockIdx.y, bn = blockIdx.x;

    // loader mapping: 256 threads load 128x8 tile as float4
    const int lr = tid >> 1;            // 0..127
    const int lc = (tid & 1) * 4;       // 0 or 4
    const int gm = bm * 128 + lr;

    // Resolve A pointer INSIDE the kernel (device-global address is only
    // valid in device code).
    const float* A = QKV ? Ain : (const float*)g_att;
    size_t arow = QKV ? (size_t)g_rowidx[gm] * CCH : (size_t)gm * CCH;
    const float* aptr = A + arow + lc;
    const float* bptr = W + (size_t)(bn * 128 + lr) * CCH + lc;

    const int ty = tid >> 4, tx = tid & 15;

    float acc[8][8];
#pragma unroll
    for (int i = 0; i < 8; i++)
#pragma unroll
        for (int j = 0; j < 8; j++) acc[i][j] = 0.f;

    // prologue: tile 0
    float4 a4 = *(const float4*)aptr;
    float4 b4 = *(const float4*)bptr;
    As[0][lc + 0][lr] = a4.x; As[0][lc + 1][lr] = a4.y;
    As[0][lc + 2][lr] = a4.z; As[0][lc + 3][lr] = a4.w;
    Bs[0][lc + 0][lr] = b4.x; Bs[0][lc + 1][lr] = b4.y;
    Bs[0][lc + 2][lr] = b4.z; Bs[0][lc + 3][lr] = b4.w;
    __syncthreads();

    int buf = 0;
    const int KTILES = CCH / 8;    // 64
    for (int kt = 0; kt < KTILES; kt++) {
        float4 na, nb;
        if (kt + 1 < KTILES) {
            na = *(const float4*)(aptr + (kt + 1) * 8);
            nb = *(const float4*)(bptr + (kt + 1) * 8);
        }
#pragma unroll
        for (int k = 0; k < 8; k++) {
            float a[8], b[8];
            *(float4*)(a)     = *(const float4*)&As[buf][k][ty * 8];
            *(float4*)(a + 4) = *(const float4*)&As[buf][k][ty * 8 + 4];
            *(float4*)(b)     = *(const float4*)&Bs[buf][k][tx * 8];
            *(float4*)(b + 4) = *(const float4*)&Bs[buf][k][tx * 8 + 4];
#pragma unroll
            for (int i = 0; i < 8; i++)
#pragma unroll
                for (int j = 0; j < 8; j++)
                    acc[i][j] = fmaf(a[i], b[j], acc[i][j]);
        }
        if (kt + 1 < KTILES) {
            int nbuf = buf ^ 1;
            As[nbuf][lc + 0][lr] = na.x; As[nbuf][lc + 1][lr] = na.y;
            As[nbuf][lc + 2][lr] = na.z; As[nbuf][lc + 3][lr] = na.w;
            Bs[nbuf][lc + 0][lr] = nb.x; Bs[nbuf][lc + 1][lr] = nb.y;
            Bs[nbuf][lc + 2][lr] = nb.z; Bs[nbuf][lc + 3][lr] = nb.w;
            __syncthreads();
            buf = nbuf;
        }
    }

    // epilogue
    const int col = bn * 128 + tx * 8;
    float4 bs0 = *(const float4*)(bias + col);
    float4 bs1 = *(const float4*)(bias + col + 4);
#pragma unroll
    for (int i = 0; i < 8; i++) {
        int m = bm * 128 + ty * 8 + i;
        float* cp;
        if (QKV) cp = g_qkv + (size_t)m * QKVC + col;
        else     cp = out   + (size_t)g_rowidx[m] * CCH + col;
        float4 r0, r1;
        r0.x = acc[i][0] + bs0.x; r0.y = acc[i][1] + bs0.y;
        r0.z = acc[i][2] + bs0.z; r0.w = acc[i][3] + bs0.w;
        r1.x = acc[i][4] + bs1.x; r1.y = acc[i][5] + bs1.y;
        r1.z = acc[i][6] + bs1.z; r1.w = acc[i][7] + bs1.w;
        *(float4*)(cp)     = r0;
        *(float4*)(cp + 4) = r1;
    }
}

// ---------------------------------------------------------------------------
// Attention: one block per (window, head). 256 threads.
// q/k/v in smem (row stride 33 -> conflict-free column access), scores 49x49,
// rel-pos bias from per-head smem-cached table, analytic shift mask, softmax,
// P@V, write g_att[(win*49+n)*512 + h*32 + d].
// ---------------------------------------------------------------------------
#define QKS 33   // smem row stride for q/k/v

__global__ __launch_bounds__(256)
void attn_kernel(const float* __restrict__ rel)
{
    const int win = blockIdx.x >> 4;
    const int h   = blockIdx.x & 15;
    const int tid = threadIdx.x;

    __shared__ float qs[NTOK * QKS];
    __shared__ float ks[NTOK * QKS];
    __shared__ float vs[NTOK * QKS];
    __shared__ float S[NTOK][50];
    __shared__ float tb[169];
    __shared__ int   lab[NTOK];

    const float scale = 0.17677669529663687f;   // 32^-0.5
    const size_t base = (size_t)win * NTOK * QKVC + h * HD;

    // load q (scaled), k, v : 49 rows x 8 float4 each
    for (int e = tid; e < NTOK * 8; e += 256) {
        int n = e >> 3, c4 = (e & 7) * 4;
        const float* p = g_qkv + base + (size_t)n * QKVC + c4;
        float4 q4 = *(const float4*)(p);
        float4 k4 = *(const float4*)(p + 512);
        float4 v4 = *(const float4*)(p + 1024);
        float* qd = &qs[n * QKS + c4];
        float* kd = &ks[n * QKS + c4];
        float* vd = &vs[n * QKS + c4];
        qd[0] = q4.x * scale; qd[1] = q4.y * scale;
        qd[2] = q4.z * scale; qd[3] = q4.w * scale;
        kd[0] = k4.x; kd[1] = k4.y; kd[2] = k4.z; kd[3] = k4.w;
        vd[0] = v4.x; vd[1] = v4.y; vd[2] = v4.z; vd[3] = v4.w;
    }
    if (tid < 169) tb[tid] = rel[tid * NHEAD + h];
    if (tid < NTOK) {
        int wi = win & 63;
        int r = (wi >> 3) * WS + tid / WS;
        int c = (wi & 7) * WS + tid % WS;
        int rh = (r < IMG - WS) ? 0 : (r < IMG - SS ? 1 : 2);
        int rw = (c < IMG - WS) ? 0 : (c < IMG - SS ? 1 : 2);
        lab[tid] = rh * 3 + rw;
    }
    __syncthreads();

    // scores + bias + mask
    for (int e = tid; e < NTOK * NTOK; e += 256) {
        int n = e / NTOK, mm = e - n * NTOK;
        const float* qp = &qs[n * QKS];
        const float* kp = &ks[mm * QKS];
        float a = 0.f;
#pragma unroll
        for (int d = 0; d < HD; d++) a = fmaf(qp[d], kp[d], a);
        int dr = n / WS - mm / WS + (WS - 1);
        int dc = n % WS - mm % WS + (WS - 1);
        a += tb[dr * (2 * WS - 1) + dc];
        if (lab[n] != lab[mm]) a -= 100.0f;
        S[n][mm] = a;
    }
    __syncthreads();

    // row softmax: warp per row (strided)
    const int warp = tid >> 5, lane = tid & 31;
    for (int n = warp; n < NTOK; n += 8) {
        float v0 = (lane < NTOK)      ? S[n][lane]      : -1e30f;
        float v1 = (lane + 32 < NTOK) ? S[n][lane + 32] : -1e30f;
        float mx = fmaxf(v0, v1);
#pragma unroll
        for (int o = 16; o > 0; o >>= 1)
            mx = fmaxf(mx, __shfl_xor_sync(0xffffffffu, mx, o));
        float e0 = (lane < NTOK)      ? __expf(v0 - mx) : 0.f;
        float e1 = (lane + 32 < NTOK) ? __expf(v1 - mx) : 0.f;
        float sm = e0 + e1;
#pragma unroll
        for (int o = 16; o > 0; o >>= 1)
            sm += __shfl_xor_sync(0xffffffffu, sm, o);
        float inv = 1.0f / sm;
        if (lane < NTOK)      S[n][lane]      = e0 * inv;
        if (lane + 32 < NTOK) S[n][lane + 32] = e1 * inv;
    }
    __syncthreads();

    // out = P @ V  -> g_att
    const size_t obase = (size_t)win * NTOK * CCH + h * HD;
    for (int e = tid; e < NTOK * HD; e += 256) {
        int n = e >> 5, d = e & 31;
        float a = 0.f;
#pragma unroll
        for (int mm = 0; mm < NTOK; mm++)
            a = fmaf(S[n][mm], vs[mm * QKS + d], a);
        g_att[obase + (size_t)n * CCH + d] = a;
    }
}

// ---------------------------------------------------------------------------
extern "C" void kernel_launch(void* const* d_in, const int* in_sizes, int n_in,
                              void* d_out, int out_size)
{
    const float* x      = (const float*)d_in[0];
    const float* qkv_w  = (const float*)d_in[1];
    const float* qkv_b  = (const float*)d_in[2];
    const float* proj_w = (const float*)d_in[3];
    const float* proj_b = (const float*)d_in[4];
    const float* rel    = (const float*)d_in[5];
    float* out = (float*)d_out;

    build_rowidx_kernel<<<(MROWS + 255) / 256, 256>>>();

    // QKV: M=100352, N=1536, gather-A from x
    gemm_kernel<true><<<dim3(QKVC / 128, MROWS / 128), 256>>>(x, qkv_w, qkv_b, nullptr);

    // attention: (window, head) blocks
    attn_kernel<<<TOTWIN * NHEAD, 256>>>(rel);

    // proj: M=100352, N=512, A = g_att (resolved in-kernel), scatter to out
    gemm_kernel<false><<<dim3(CCH / 128, MROWS / 128), 256>>>(nullptr, proj_w, proj_b, out);
}

// round 5
// speedup vs baseline: 1.0085x; 1.0085x over previous
#include <cuda_runtime.h>
#include <cuda_bf16.h>
#include <cstdint>

// ---------------------------------------------------------------------------
// Swin shifted-window attention, B=32 H=W=56 C=512 NH=16 HD=32 WS=7 SS=3
// fp32 SIMT pipeline:
//   k0: build row-index table (shift + window partition bijection)
//   k1: QKV GEMM  (gather-A)    X[100352,512] @ Wqkv^T[512,1536] + b -> g_qkv
//   k2: attention per (window, head)                              -> g_att
//   k3: proj GEMM (A = g_att global, scatter-C) @ Wp^T + b        -> out
//
// FIX vs previous round: the proj GEMM was receiving the HOST shadow address
// of the __device__ global g_att (passed as a kernel argument from host
// code). On GB300, ATS made that a silent read of zero host memory instead
// of a fault. The PROJ path now references g_att directly inside the kernel.
// ---------------------------------------------------------------------------

#define BATCH   32
#define IMG     56
#define CCH     512
#define NHEAD   16
#define HD      32
#define WS      7
#define SS      3
#define NTOK    49            // WS*WS
#define NWH     8             // IMG/WS
#define NWIN    64            // per image
#define TOTWIN  2048          // BATCH*NWIN
#define MROWS   100352        // TOTWIN*NTOK
#define QKVC    1536

// scratch (device globals: allocation-free)
__device__ float g_qkv[(size_t)MROWS * QKVC];   // 617 MB
__device__ float g_att[(size_t)MROWS * CCH];    // 205 MB
__device__ int   g_rowidx[MROWS];

// ---------------------------------------------------------------------------
__global__ void build_rowidx_kernel() {
    int m = blockIdx.x * 256 + threadIdx.x;
    if (m >= MROWS) return;
    int win = m / NTOK, n = m % NTOK;
    int b  = win >> 6, wi = win & 63;
    int wh = wi >> 3,  ww = wi & 7;
    int r = wh * WS + n / WS;
    int c = ww * WS + n % WS;
    int sh = r + SS; if (sh >= IMG) sh -= IMG;
    int sw = c + SS; if (sw >= IMG) sw -= IMG;
    g_rowidx[m] = (b * IMG + sh) * IMG + sw;
}

// ---------------------------------------------------------------------------
// Tiled fp32 GEMM: C[M,N] = A[M,512] * W[N,512]^T + bias[N]
// BM=BN=128, BK=8, 256 threads, 8x8 per-thread tile, double-buffered smem.
// QKV mode: A = x (param), rows gathered via g_rowidx, C -> g_qkv (ld 1536).
// PROJ mode: A = g_att (device global, addressed IN-KERNEL),
//            C scattered through g_rowidx into out.
// ---------------------------------------------------------------------------
template <bool QKV>
__global__ __launch_bounds__(256, 2)
void gemm_kernel(const float* __restrict__ Ain,
                 const float* __restrict__ W,
                 const float* __restrict__ bias,
                 float* __restrict__ out)
{
    __shared__ float As[2][8][128];
    __shared__ float Bs[2][8][128];

    const int tid = threadIdx.x;
    const int bm = blockIdx.y, bn = blockIdx.x;

    // loader mapping: 256 threads load 128x8 tile as float4
    const int lr = tid >> 1;            // 0..127
    const int lc = (tid & 1) * 4;       // 0 or 4
    const int gm = bm * 128 + lr;

    // Resolve A pointer INSIDE the kernel (device-global address is only
    // valid in device code).
    const float* A = QKV ? Ain : (const float*)g_att;
    size_t arow = QKV ? (size_t)g_rowidx[gm] * CCH : (size_t)gm * CCH;
    const float* aptr = A + arow + lc;
    const float* bptr = W + (size_t)(bn * 128 + lr) * CCH + lc;

    const int ty = tid >> 4, tx = tid & 15;

    float acc[8][8];
#pragma unroll
    for (int i = 0; i < 8; i++)
#pragma unroll
        for (int j = 0; j < 8; j++) acc[i][j] = 0.f;

    // prologue: tile 0
    float4 a4 = *(const float4*)aptr;
    float4 b4 = *(const float4*)bptr;
    As[0][lc + 0][lr] = a4.x; As[0][lc + 1][lr] = a4.y;
    As[0][lc + 2][lr] = a4.z; As[0][lc + 3][lr] = a4.w;
    Bs[0][lc + 0][lr] = b4.x; Bs[0][lc + 1][lr] = b4.y;
    Bs[0][lc + 2][lr] = b4.z; Bs[0][lc + 3][lr] = b4.w;
    __syncthreads();

    int buf = 0;
    const int KTILES = CCH / 8;    // 64
    for (int kt = 0; kt < KTILES; kt++) {
        float4 na, nb;
        if (kt + 1 < KTILES) {
            na = *(const float4*)(aptr + (kt + 1) * 8);
            nb = *(const float4*)(bptr + (kt + 1) * 8);
        }
#pragma unroll
        for (int k = 0; k < 8; k++) {
            float a[8], b[8];
            *(float4*)(a)     = *(const float4*)&As[buf][k][ty * 8];
            *(float4*)(a + 4) = *(const float4*)&As[buf][k][ty * 8 + 4];
            *(float4*)(b)     = *(const float4*)&Bs[buf][k][tx * 8];
            *(float4*)(b + 4) = *(const float4*)&Bs[buf][k][tx * 8 + 4];
#pragma unroll
            for (int i = 0; i < 8; i++)
#pragma unroll
                for (int j = 0; j < 8; j++)
                    acc[i][j] = fmaf(a[i], b[j], acc[i][j]);
        }
        if (kt + 1 < KTILES) {
            int nbuf = buf ^ 1;
            As[nbuf][lc + 0][lr] = na.x; As[nbuf][lc + 1][lr] = na.y;
            As[nbuf][lc + 2][lr] = na.z; As[nbuf][lc + 3][lr] = na.w;
            Bs[nbuf][lc + 0][lr] = nb.x; Bs[nbuf][lc + 1][lr] = nb.y;
            Bs[nbuf][lc + 2][lr] = nb.z; Bs[nbuf][lc + 3][lr] = nb.w;
            __syncthreads();
            buf = nbuf;
        }
    }

    // epilogue
    const int col = bn * 128 + tx * 8;
    float4 bs0 = *(const float4*)(bias + col);
    float4 bs1 = *(const float4*)(bias + col + 4);
#pragma unroll
    for (int i = 0; i < 8; i++) {
        int m = bm * 128 + ty * 8 + i;
        float* cp;
        if (QKV) cp = g_qkv + (size_t)m * QKVC + col;
        else     cp = out   + (size_t)g_rowidx[m] * CCH + col;
        float4 r0, r1;
        r0.x = acc[i][0] + bs0.x; r0.y = acc[i][1] + bs0.y;
        r0.z = acc[i][2] + bs0.z; r0.w = acc[i][3] + bs0.w;
        r1.x = acc[i][4] + bs1.x; r1.y = acc[i][5] + bs1.y;
        r1.z = acc[i][6] + bs1.z; r1.w = acc[i][7] + bs1.w;
        *(float4*)(cp)     = r0;
        *(float4*)(cp + 4) = r1;
    }
}

// ---------------------------------------------------------------------------
// Attention: one block per (window, head). 256 threads.
// q/k/v in smem (row stride 33 -> conflict-free column access), scores 49x49,
// rel-pos bias from per-head smem-cached table, analytic shift mask, softmax,
// P@V, write g_att[(win*49+n)*512 + h*32 + d].
// ---------------------------------------------------------------------------
#define QKS 33   // smem row stride for q/k/v

__global__ __launch_bounds__(256)
void attn_kernel(const float* __restrict__ rel)
{
    const int win = blockIdx.x >> 4;
    const int h   = blockIdx.x & 15;
    const int tid = threadIdx.x;

    __shared__ float qs[NTOK * QKS];
    __shared__ float ks[NTOK * QKS];
    __shared__ float vs[NTOK * QKS];
    __shared__ float S[NTOK][50];
    __shared__ float tb[169];
    __shared__ int   lab[NTOK];

    const float scale = 0.17677669529663687f;   // 32^-0.5
    const size_t base = (size_t)win * NTOK * QKVC + h * HD;

    // load q (scaled), k, v : 49 rows x 8 float4 each
    for (int e = tid; e < NTOK * 8; e += 256) {
        int n = e >> 3, c4 = (e & 7) * 4;
        const float* p = g_qkv + base + (size_t)n * QKVC + c4;
        float4 q4 = *(const float4*)(p);
        float4 k4 = *(const float4*)(p + 512);
        float4 v4 = *(const float4*)(p + 1024);
        float* qd = &qs[n * QKS + c4];
        float* kd = &ks[n * QKS + c4];
        float* vd = &vs[n * QKS + c4];
        qd[0] = q4.x * scale; qd[1] = q4.y * scale;
        qd[2] = q4.z * scale; qd[3] = q4.w * scale;
        kd[0] = k4.x; kd[1] = k4.y; kd[2] = k4.z; kd[3] = k4.w;
        vd[0] = v4.x; vd[1] = v4.y; vd[2] = v4.z; vd[3] = v4.w;
    }
    if (tid < 169) tb[tid] = rel[tid * NHEAD + h];
    if (tid < NTOK) {
        int wi = win & 63;
        int r = (wi >> 3) * WS + tid / WS;
        int c = (wi & 7) * WS + tid % WS;
        int rh = (r < IMG - WS) ? 0 : (r < IMG - SS ? 1 : 2);
        int rw = (c < IMG - WS) ? 0 : (c < IMG - SS ? 1 : 2);
        lab[tid] = rh * 3 + rw;
    }
    __syncthreads();

    // scores + bias + mask
    for (int e = tid; e < NTOK * NTOK; e += 256) {
        int n = e / NTOK, mm = e - n * NTOK;
        const float* qp = &qs[n * QKS];
        const float* kp = &ks[mm * QKS];
        float a = 0.f;
#pragma unroll
        for (int d = 0; d < HD; d++) a = fmaf(qp[d], kp[d], a);
        int dr = n / WS - mm / WS + (WS - 1);
        int dc = n % WS - mm % WS + (WS - 1);
        a += tb[dr * (2 * WS - 1) + dc];
        if (lab[n] != lab[mm]) a -= 100.0f;
        S[n][mm] = a;
    }
    __syncthreads();

    // row softmax: warp per row (strided)
    const int warp = tid >> 5, lane = tid & 31;
    for (int n = warp; n < NTOK; n += 8) {
        float v0 = (lane < NTOK)      ? S[n][lane]      : -1e30f;
        float v1 = (lane + 32 < NTOK) ? S[n][lane + 32] : -1e30f;
        float mx = fmaxf(v0, v1);
#pragma unroll
        for (int o = 16; o > 0; o >>= 1)
            mx = fmaxf(mx, __shfl_xor_sync(0xffffffffu, mx, o));
        float e0 = (lane < NTOK)      ? __expf(v0 - mx) : 0.f;
        float e1 = (lane + 32 < NTOK) ? __expf(v1 - mx) : 0.f;
        float sm = e0 + e1;
#pragma unroll
        for (int o = 16; o > 0; o >>= 1)
            sm += __shfl_xor_sync(0xffffffffu, sm, o);
        float inv = 1.0f / sm;
        if (lane < NTOK)      S[n][lane]      = e0 * inv;
        if (lane + 32 < NTOK) S[n][lane + 32] = e1 * inv;
    }
    __syncthreads();

    // out = P @ V  -> g_att
    const size_t obase = (size_t)win * NTOK * CCH + h * HD;
    for (int e = tid; e < NTOK * HD; e += 256) {
        int n = e >> 5, d = e & 31;
        float a = 0.f;
#pragma unroll
        for (int mm = 0; mm < NTOK; mm++)
            a = fmaf(S[n][mm], vs[mm * QKS + d], a);
        g_att[obase + (size_t)n * CCH + d] = a;
    }
}

// ---------------------------------------------------------------------------
extern "C" void kernel_launch(void* const* d_in, const int* in_sizes, int n_in,
                              void* d_out, int out_size)
{
    const float* x      = (const float*)d_in[0];
    const float* qkv_w  = (const float*)d_in[1];
    const float* qkv_b  = (const float*)d_in[2];
    const float* proj_w = (const float*)d_in[3];
    const float* proj_b = (const float*)d_in[4];
    const float* rel    = (const float*)d_in[5];
    float* out = (float*)d_out;

    build_rowidx_kernel<<<(MROWS + 255) / 256, 256>>>();

    // QKV: M=100352, N=1536, gather-A from x
    gemm_kernel<true><<<dim3(QKVC / 128, MROWS / 128), 256>>>(x, qkv_w, qkv_b, nullptr);

    // attention: (window, head) blocks
    attn_kernel<<<TOTWIN * NHEAD, 256>>>(rel);

    // proj: M=100352, N=512, A = g_att (resolved in-kernel), scatter to out
    gemm_kernel<false><<<dim3(CCH / 128, MROWS / 128), 256>>>(nullptr, proj_w, proj_b, out);
}